// round 5
// baseline (speedup 1.0000x reference)
#include <cuda_runtime.h>

#define N_I 500000
#define N_H 200000
#define F_I 32
#define F_H 16
#define EF  8
#define E1  2000000
#define E2  2000000

// Scratch (static device globals — no runtime allocation).
__device__ float g_y_house[(size_t)N_H * EF];
__device__ float g_s_house[N_H];
__device__ float g_y_indivi[(size_t)N_I * EF];
__device__ float g_s_indivi[N_I];

// ---------------------------------------------------------------------------
// prep_house: y_house[n,k] = sum_f x_house[n,f] * W_edge_h2i[f,k]
//             s_house[n]   = dot(x_house[n], b_edge_h2i)
// ---------------------------------------------------------------------------
__global__ void prep_house_kernel(const float* __restrict__ x,
                                  const float* __restrict__ W,   // [F_H, EF]
                                  const float* __restrict__ b) { // [F_H]
    __shared__ float sW[F_H * EF];
    __shared__ float sb[F_H];
    int t = threadIdx.x;
    if (t < F_H * EF) sW[t] = W[t];
    if (t < F_H)      sb[t] = b[t];
    __syncthreads();

    int n = blockIdx.x * blockDim.x + t;
    if (n >= N_H) return;

    float xr[F_H];
    const float4* xp = (const float4*)(x + (size_t)n * F_H);
#pragma unroll
    for (int i = 0; i < F_H / 4; i++) {
        float4 v = __ldg(xp + i);
        xr[4*i+0] = v.x; xr[4*i+1] = v.y; xr[4*i+2] = v.z; xr[4*i+3] = v.w;
    }

    float y[EF];
#pragma unroll
    for (int k = 0; k < EF; k++) y[k] = 0.f;
    float s = 0.f;
#pragma unroll
    for (int f = 0; f < F_H; f++) {
        s = fmaf(xr[f], sb[f], s);
#pragma unroll
        for (int k = 0; k < EF; k++) y[k] = fmaf(xr[f], sW[f * EF + k], y[k]);
    }

    float4* yp = (float4*)(g_y_house + (size_t)n * EF);
    yp[0] = make_float4(y[0], y[1], y[2], y[3]);
    yp[1] = make_float4(y[4], y[5], y[6], y[7]);
    g_s_house[n] = s;
}

// ---------------------------------------------------------------------------
// prep_indivi: y_indivi/s_indivi (W_edge_i2i, b_edge_i2i) + fused root term:
//   out[n] = dot(x_indivi[n], W_root_h2i + W_root_i2i) + bias_h2i + bias_i2i
// ---------------------------------------------------------------------------
__global__ void prep_indivi_kernel(const float* __restrict__ x,
                                   const float* __restrict__ W,    // [F_I, EF]
                                   const float* __restrict__ b,    // [F_I]
                                   const float* __restrict__ wr1,  // [F_I]
                                   const float* __restrict__ wr2,  // [F_I]
                                   const float* __restrict__ bias1,// [1]
                                   const float* __restrict__ bias2,// [1]
                                   float* __restrict__ out) {
    __shared__ float sW[F_I * EF];
    __shared__ float sb[F_I];
    __shared__ float swr[F_I];
    int t = threadIdx.x;
    if (t < F_I * EF) sW[t] = W[t];
    if (t < F_I) {
        sb[t]  = b[t];
        swr[t] = wr1[t] + wr2[t];
    }
    __syncthreads();

    int n = blockIdx.x * blockDim.x + t;
    if (n >= N_I) return;

    float xr[F_I];
    const float4* xp = (const float4*)(x + (size_t)n * F_I);
#pragma unroll
    for (int i = 0; i < F_I / 4; i++) {
        float4 v = __ldg(xp + i);
        xr[4*i+0] = v.x; xr[4*i+1] = v.y; xr[4*i+2] = v.z; xr[4*i+3] = v.w;
    }

    float y[EF];
#pragma unroll
    for (int k = 0; k < EF; k++) y[k] = 0.f;
    float s = 0.f, r = 0.f;
#pragma unroll
    for (int f = 0; f < F_I; f++) {
        s = fmaf(xr[f], sb[f], s);
        r = fmaf(xr[f], swr[f], r);
#pragma unroll
        for (int k = 0; k < EF; k++) y[k] = fmaf(xr[f], sW[f * EF + k], y[k]);
    }

    float4* yp = (float4*)(g_y_indivi + (size_t)n * EF);
    yp[0] = make_float4(y[0], y[1], y[2], y[3]);
    yp[1] = make_float4(y[4], y[5], y[6], y[7]);
    g_s_indivi[n] = s;
    out[n] = r + __ldg(bias1) + __ldg(bias2);
}

// ---------------------------------------------------------------------------
// edge kernel: one thread per edge, scratch selected at compile time so no
// symbol-address lookup is needed on the host side.
//   msg = s[src] + dot8(y[src], edge_attr[e]);  atomicAdd(out[dst], msg)
// ---------------------------------------------------------------------------
template <bool USE_HOUSE>
__global__ void edge_kernel(const float* __restrict__ ea,
                            const int* __restrict__ src,
                            const int* __restrict__ dst,
                            float* __restrict__ out,
                            int E) {
    int e = blockIdx.x * blockDim.x + threadIdx.x;
    if (e >= E) return;

    const float* __restrict__ y = USE_HOUSE ? g_y_house : g_y_indivi;
    const float* __restrict__ s = USE_HOUSE ? g_s_house : g_s_indivi;

    int si = __ldg(src + e);
    int di = __ldg(dst + e);

    const float4* ep = (const float4*)(ea + (size_t)e * EF);
    float4 a0 = __ldg(ep + 0);
    float4 a1 = __ldg(ep + 1);

    const float4* yp = (const float4*)(y + (size_t)si * EF);
    float4 y0 = __ldg(yp + 0);
    float4 y1 = __ldg(yp + 1);

    float msg = __ldg(s + si);
    msg = fmaf(a0.x, y0.x, msg);
    msg = fmaf(a0.y, y0.y, msg);
    msg = fmaf(a0.z, y0.z, msg);
    msg = fmaf(a0.w, y0.w, msg);
    msg = fmaf(a1.x, y1.x, msg);
    msg = fmaf(a1.y, y1.y, msg);
    msg = fmaf(a1.z, y1.z, msg);
    msg = fmaf(a1.w, y1.w, msg);

    atomicAdd(out + di, msg);
}

// ---------------------------------------------------------------------------
// launch — kernel launches ONLY (graph-capture clean)
// ---------------------------------------------------------------------------
extern "C" void kernel_launch(void* const* d_in, const int* in_sizes, int n_in,
                              void* d_out, int out_size) {
    const float* x_indivi      = (const float*)d_in[0];
    const float* x_house       = (const float*)d_in[1];
    const float* edge_attr_h2i = (const float*)d_in[2];
    const float* edge_attr_i2i = (const float*)d_in[3];
    const float* W_edge_h2i    = (const float*)d_in[4];
    const float* b_edge_h2i    = (const float*)d_in[5];
    const float* W_edge_i2i    = (const float*)d_in[6];
    const float* b_edge_i2i    = (const float*)d_in[7];
    const float* W_root_h2i    = (const float*)d_in[8];
    const float* bias_h2i      = (const float*)d_in[9];
    const float* W_root_i2i    = (const float*)d_in[10];
    const float* bias_i2i      = (const float*)d_in[11];
    const int*   src_h2i       = (const int*)d_in[12];
    const int*   dst_h2i       = (const int*)d_in[13];
    const int*   src_i2i       = (const int*)d_in[14];
    const int*   dst_i2i       = (const int*)d_in[15];
    float* out = (float*)d_out;

    const int TPB = 256;

    prep_house_kernel<<<(N_H + TPB - 1) / TPB, TPB>>>(x_house, W_edge_h2i, b_edge_h2i);
    prep_indivi_kernel<<<(N_I + TPB - 1) / TPB, TPB>>>(x_indivi, W_edge_i2i, b_edge_i2i,
                                                       W_root_h2i, W_root_i2i,
                                                       bias_h2i, bias_i2i, out);
    edge_kernel<true><<<(E1 + TPB - 1) / TPB, TPB>>>(edge_attr_h2i, src_h2i, dst_h2i,
                                                     out, E1);
    edge_kernel<false><<<(E2 + TPB - 1) / TPB, TPB>>>(edge_attr_i2i, src_i2i, dst_i2i,
                                                      out, E2);
}

// round 6
// speedup vs baseline: 1.0292x; 1.0292x over previous
#include <cuda_runtime.h>

#define N_I 500000
#define N_H 200000
#define F_I 32
#define F_H 16
#define EF  8
#define E1  2000000
#define E2  2000000

#define TPB 256
#define EPT 2   // edges per thread

// Scratch (static device globals — no runtime allocation).
__device__ float g_y_house[(size_t)N_H * EF];
__device__ float g_s_house[N_H];
__device__ float g_y_indivi[(size_t)N_I * EF];
__device__ float g_s_indivi[N_I];

// block counts
#define NB_I   ((N_I + TPB - 1) / TPB)                 // indivi prep blocks
#define NB_H   ((N_H + TPB - 1) / TPB)                 // house prep blocks
#define NBE_1  ((E1 + TPB * EPT - 1) / (TPB * EPT))    // h2i edge blocks
#define NBE_2  ((E2 + TPB * EPT - 1) / (TPB * EPT))    // i2i edge blocks

// ---------------------------------------------------------------------------
// Fused prep: blocks [0, NB_I) handle indivi (+ root/bias -> out init),
//             blocks [NB_I, NB_I+NB_H) handle house.
// ---------------------------------------------------------------------------
__global__ void prep_fused_kernel(const float* __restrict__ x_i,
                                  const float* __restrict__ W_i,   // [F_I, EF]
                                  const float* __restrict__ b_i,   // [F_I]
                                  const float* __restrict__ wr1,   // [F_I]
                                  const float* __restrict__ wr2,   // [F_I]
                                  const float* __restrict__ bias1, // [1]
                                  const float* __restrict__ bias2, // [1]
                                  const float* __restrict__ x_h,
                                  const float* __restrict__ W_h,   // [F_H, EF]
                                  const float* __restrict__ b_h,   // [F_H]
                                  float* __restrict__ out) {
    __shared__ float sW[F_I * EF];   // 256 floats (reused: 128 for house)
    __shared__ float sb[F_I];
    __shared__ float swr[F_I];
    int t = threadIdx.x;

    if (blockIdx.x < NB_I) {
        // ---------------- indivi branch ----------------
        if (t < F_I * EF) sW[t] = W_i[t];
        if (t < F_I) {
            sb[t]  = b_i[t];
            swr[t] = wr1[t] + wr2[t];
        }
        __syncthreads();

        int n = blockIdx.x * TPB + t;
        if (n >= N_I) return;

        float xr[F_I];
        const float4* xp = (const float4*)(x_i + (size_t)n * F_I);
#pragma unroll
        for (int i = 0; i < F_I / 4; i++) {
            float4 v = __ldg(xp + i);
            xr[4*i+0] = v.x; xr[4*i+1] = v.y; xr[4*i+2] = v.z; xr[4*i+3] = v.w;
        }

        float y[EF];
#pragma unroll
        for (int k = 0; k < EF; k++) y[k] = 0.f;
        float s = 0.f, r = 0.f;
#pragma unroll
        for (int f = 0; f < F_I; f++) {
            s = fmaf(xr[f], sb[f], s);
            r = fmaf(xr[f], swr[f], r);
#pragma unroll
            for (int k = 0; k < EF; k++) y[k] = fmaf(xr[f], sW[f * EF + k], y[k]);
        }

        float4* yp = (float4*)(g_y_indivi + (size_t)n * EF);
        yp[0] = make_float4(y[0], y[1], y[2], y[3]);
        yp[1] = make_float4(y[4], y[5], y[6], y[7]);
        g_s_indivi[n] = s;
        out[n] = r + __ldg(bias1) + __ldg(bias2);
    } else {
        // ---------------- house branch ----------------
        if (t < F_H * EF) sW[t] = W_h[t];
        if (t < F_H)      sb[t] = b_h[t];
        __syncthreads();

        int n = (blockIdx.x - NB_I) * TPB + t;
        if (n >= N_H) return;

        float xr[F_H];
        const float4* xp = (const float4*)(x_h + (size_t)n * F_H);
#pragma unroll
        for (int i = 0; i < F_H / 4; i++) {
            float4 v = __ldg(xp + i);
            xr[4*i+0] = v.x; xr[4*i+1] = v.y; xr[4*i+2] = v.z; xr[4*i+3] = v.w;
        }

        float y[EF];
#pragma unroll
        for (int k = 0; k < EF; k++) y[k] = 0.f;
        float s = 0.f;
#pragma unroll
        for (int f = 0; f < F_H; f++) {
            s = fmaf(xr[f], sb[f], s);
#pragma unroll
            for (int k = 0; k < EF; k++) y[k] = fmaf(xr[f], sW[f * EF + k], y[k]);
        }

        float4* yp = (float4*)(g_y_house + (size_t)n * EF);
        yp[0] = make_float4(y[0], y[1], y[2], y[3]);
        yp[1] = make_float4(y[4], y[5], y[6], y[7]);
        g_s_house[n] = s;
    }
}

// ---------------------------------------------------------------------------
// Per-thread edge work: EPT=2 edges, front-batched loads for max MLP.
// ---------------------------------------------------------------------------
__device__ __forceinline__ void edge_work2(const float* __restrict__ ea,
                                           const int* __restrict__ src,
                                           const int* __restrict__ dst,
                                           const float* __restrict__ y,
                                           const float* __restrict__ s,
                                           float* __restrict__ out,
                                           int e0, int E) {
    if (e0 >= E) return;   // E is even, e0 is even -> both edges valid

    // front-batch all independent loads
    int2 s2 = __ldg((const int2*)(src + e0));
    int2 d2 = __ldg((const int2*)(dst + e0));

    const float4* ep = (const float4*)(ea + (size_t)e0 * EF);
    float4 a0 = __ldg(ep + 0);
    float4 a1 = __ldg(ep + 1);
    float4 a2 = __ldg(ep + 2);
    float4 a3 = __ldg(ep + 3);

    // two independent gather chains
    const float4* yp0 = (const float4*)(y + (size_t)s2.x * EF);
    const float4* yp1 = (const float4*)(y + (size_t)s2.y * EF);
    float4 y00 = __ldg(yp0 + 0);
    float4 y01 = __ldg(yp0 + 1);
    float4 y10 = __ldg(yp1 + 0);
    float4 y11 = __ldg(yp1 + 1);
    float  s0  = __ldg(s + s2.x);
    float  s1  = __ldg(s + s2.y);

    float m0 = s0;
    m0 = fmaf(a0.x, y00.x, m0); m0 = fmaf(a0.y, y00.y, m0);
    m0 = fmaf(a0.z, y00.z, m0); m0 = fmaf(a0.w, y00.w, m0);
    m0 = fmaf(a1.x, y01.x, m0); m0 = fmaf(a1.y, y01.y, m0);
    m0 = fmaf(a1.z, y01.z, m0); m0 = fmaf(a1.w, y01.w, m0);

    float m1 = s1;
    m1 = fmaf(a2.x, y10.x, m1); m1 = fmaf(a2.y, y10.y, m1);
    m1 = fmaf(a2.z, y10.z, m1); m1 = fmaf(a2.w, y10.w, m1);
    m1 = fmaf(a3.x, y11.x, m1); m1 = fmaf(a3.y, y11.y, m1);
    m1 = fmaf(a3.z, y11.z, m1); m1 = fmaf(a3.w, y11.w, m1);

    atomicAdd(out + d2.x, m0);
    atomicAdd(out + d2.y, m1);
}

// ---------------------------------------------------------------------------
// Fused edge kernel: blocks [0, NBE_1) -> h2i, [NBE_1, NBE_1+NBE_2) -> i2i.
// Both relations in flight simultaneously (atomics commute).
// ---------------------------------------------------------------------------
__global__ void edge_fused_kernel(const float* __restrict__ ea1,
                                  const int* __restrict__ src1,
                                  const int* __restrict__ dst1,
                                  const float* __restrict__ ea2,
                                  const int* __restrict__ src2,
                                  const int* __restrict__ dst2,
                                  float* __restrict__ out) {
    if (blockIdx.x < NBE_1) {
        int e0 = (blockIdx.x * TPB + threadIdx.x) * EPT;
        edge_work2(ea1, src1, dst1, g_y_house, g_s_house, out, e0, E1);
    } else {
        int e0 = ((blockIdx.x - NBE_1) * TPB + threadIdx.x) * EPT;
        edge_work2(ea2, src2, dst2, g_y_indivi, g_s_indivi, out, e0, E2);
    }
}

// ---------------------------------------------------------------------------
// launch — kernel launches ONLY (graph-capture clean)
// ---------------------------------------------------------------------------
extern "C" void kernel_launch(void* const* d_in, const int* in_sizes, int n_in,
                              void* d_out, int out_size) {
    const float* x_indivi      = (const float*)d_in[0];
    const float* x_house       = (const float*)d_in[1];
    const float* edge_attr_h2i = (const float*)d_in[2];
    const float* edge_attr_i2i = (const float*)d_in[3];
    const float* W_edge_h2i    = (const float*)d_in[4];
    const float* b_edge_h2i    = (const float*)d_in[5];
    const float* W_edge_i2i    = (const float*)d_in[6];
    const float* b_edge_i2i    = (const float*)d_in[7];
    const float* W_root_h2i    = (const float*)d_in[8];
    const float* bias_h2i      = (const float*)d_in[9];
    const float* W_root_i2i    = (const float*)d_in[10];
    const float* bias_i2i      = (const float*)d_in[11];
    const int*   src_h2i       = (const int*)d_in[12];
    const int*   dst_h2i       = (const int*)d_in[13];
    const int*   src_i2i       = (const int*)d_in[14];
    const int*   dst_i2i       = (const int*)d_in[15];
    float* out = (float*)d_out;

    prep_fused_kernel<<<NB_I + NB_H, TPB>>>(x_indivi, W_edge_i2i, b_edge_i2i,
                                            W_root_h2i, W_root_i2i,
                                            bias_h2i, bias_i2i,
                                            x_house, W_edge_h2i, b_edge_h2i,
                                            out);

    edge_fused_kernel<<<NBE_1 + NBE_2, TPB>>>(edge_attr_h2i, src_h2i, dst_h2i,
                                              edge_attr_i2i, src_i2i, dst_i2i,
                                              out);
}

// round 8
// speedup vs baseline: 1.0772x; 1.0467x over previous
#include <cuda_runtime.h>
#include <cuda_fp16.h>

#define N_I 500000
#define N_H 200000
#define F_I 32
#define F_H 16
#define EF  8
#define E1  2000000
#define E2  2000000

#define TPB 256
#define EPT 2   // edges per thread

// Packed per-node scratch: 32 B/node = [8 x fp16 y | fp32 s | 12 B pad]
// float4 type guarantees 16B alignment; 2 float4 per node.
__device__ float4 g_z_house[(size_t)N_H * 2];
__device__ float4 g_z_indivi[(size_t)N_I * 2];

// block counts
#define NB_I   ((N_I + TPB - 1) / TPB)
#define NB_H   ((N_H + TPB - 1) / TPB)
#define NBE_1  ((E1 + TPB * EPT - 1) / (TPB * EPT))
#define NBE_2  ((E2 + TPB * EPT - 1) / (TPB * EPT))

// ---- packed fp32x2 helpers (Blackwell FFMA2 — PTX-only path) -------------
__device__ __forceinline__ unsigned long long pk2(float lo, float hi) {
    unsigned long long r;
    asm("mov.b64 %0, {%1, %2};" : "=l"(r) : "f"(lo), "f"(hi));
    return r;
}
__device__ __forceinline__ void upk2(float& lo, float& hi, unsigned long long v) {
    asm("mov.b64 {%0, %1}, %2;" : "=f"(lo), "=f"(hi) : "l"(v));
}
#define FFMA2(d, a, b, c) \
    asm("fma.rn.f32x2 %0, %1, %2, %3;" : "=l"(d) : "l"(a), "l"(b), "l"(c))

// ---------------------------------------------------------------------------
// Fused prep: blocks [0, NB_I) -> indivi (+ root/bias -> out init),
//             blocks [NB_I, NB_I+NB_H) -> house.
// ---------------------------------------------------------------------------
__global__ void prep_fused_kernel(const float* __restrict__ x_i,
                                  const float* __restrict__ W_i,   // [F_I, EF]
                                  const float* __restrict__ b_i,   // [F_I]
                                  const float* __restrict__ wr1,   // [F_I]
                                  const float* __restrict__ wr2,   // [F_I]
                                  const float* __restrict__ bias1, // [1]
                                  const float* __restrict__ bias2, // [1]
                                  const float* __restrict__ x_h,
                                  const float* __restrict__ W_h,   // [F_H, EF]
                                  const float* __restrict__ b_h,   // [F_H]
                                  float* __restrict__ out) {
    __shared__ unsigned long long sW2[F_I * 4];  // W packed in fp32x2 pairs
    __shared__ unsigned long long sbr[F_I];      // (b, wroot_sum) packed
    int t = threadIdx.x;

    if (blockIdx.x < NB_I) {
        // ---------------- indivi ----------------
        if (t < F_I * 4) {
            int f = t >> 2, j = t & 3;
            sW2[t] = pk2(W_i[f * EF + 2 * j], W_i[f * EF + 2 * j + 1]);
        }
        if (t < F_I) sbr[t] = pk2(b_i[t], wr1[t] + wr2[t]);
        __syncthreads();

        int n = blockIdx.x * TPB + t;
        if (n >= N_I) return;

        float xr[F_I];
        const float4* xp = (const float4*)(x_i + (size_t)n * F_I);
#pragma unroll
        for (int i = 0; i < F_I / 4; i++) {
            float4 v = __ldg(xp + i);
            xr[4*i+0] = v.x; xr[4*i+1] = v.y; xr[4*i+2] = v.z; xr[4*i+3] = v.w;
        }

        unsigned long long acc[4], asr;
#pragma unroll
        for (int j = 0; j < 4; j++) acc[j] = 0ull;
        asr = 0ull;
#pragma unroll
        for (int f = 0; f < F_I; f++) {
            unsigned long long xx = pk2(xr[f], xr[f]);
#pragma unroll
            for (int j = 0; j < 4; j++) FFMA2(acc[j], xx, sW2[f * 4 + j], acc[j]);
            FFMA2(asr, xx, sbr[f], asr);
        }

        float y[EF], s, r;
#pragma unroll
        for (int j = 0; j < 4; j++) upk2(y[2*j], y[2*j+1], acc[j]);
        upk2(s, r, asr);

        float4 v;
        __half2* hv = (__half2*)&v;
        hv[0] = __floats2half2_rn(y[0], y[1]);
        hv[1] = __floats2half2_rn(y[2], y[3]);
        hv[2] = __floats2half2_rn(y[4], y[5]);
        hv[3] = __floats2half2_rn(y[6], y[7]);
        float4* zp = &g_z_indivi[(size_t)n * 2];
        zp[0] = v;
        ((float*)(zp + 1))[0] = s;
        out[n] = r + __ldg(bias1) + __ldg(bias2);
    } else {
        // ---------------- house ----------------
        if (t < F_H * 4) {
            int f = t >> 2, j = t & 3;
            sW2[t] = pk2(W_h[f * EF + 2 * j], W_h[f * EF + 2 * j + 1]);
        }
        if (t < F_H) sbr[t] = pk2(b_h[t], 0.f);
        __syncthreads();

        int n = (blockIdx.x - NB_I) * TPB + t;
        if (n >= N_H) return;

        float xr[F_H];
        const float4* xp = (const float4*)(x_h + (size_t)n * F_H);
#pragma unroll
        for (int i = 0; i < F_H / 4; i++) {
            float4 v = __ldg(xp + i);
            xr[4*i+0] = v.x; xr[4*i+1] = v.y; xr[4*i+2] = v.z; xr[4*i+3] = v.w;
        }

        unsigned long long acc[4], asr;
#pragma unroll
        for (int j = 0; j < 4; j++) acc[j] = 0ull;
        asr = 0ull;
#pragma unroll
        for (int f = 0; f < F_H; f++) {
            unsigned long long xx = pk2(xr[f], xr[f]);
#pragma unroll
            for (int j = 0; j < 4; j++) FFMA2(acc[j], xx, sW2[f * 4 + j], acc[j]);
            FFMA2(asr, xx, sbr[f], asr);
        }

        float y[EF], s, dummy;
#pragma unroll
        for (int j = 0; j < 4; j++) upk2(y[2*j], y[2*j+1], acc[j]);
        upk2(s, dummy, asr);

        float4 v;
        __half2* hv = (__half2*)&v;
        hv[0] = __floats2half2_rn(y[0], y[1]);
        hv[1] = __floats2half2_rn(y[2], y[3]);
        hv[2] = __floats2half2_rn(y[4], y[5]);
        hv[3] = __floats2half2_rn(y[6], y[7]);
        float4* zp = &g_z_house[(size_t)n * 2];
        zp[0] = v;
        ((float*)(zp + 1))[0] = s;
    }
}

// ---------------------------------------------------------------------------
// Per-thread edge work: 2 edges, packed 32B gather (fp16 y + fp32 s, 1 sector).
// ---------------------------------------------------------------------------
__device__ __forceinline__ void edge_work2(const float* __restrict__ ea,
                                           const int* __restrict__ src,
                                           const int* __restrict__ dst,
                                           const float4* __restrict__ z,
                                           float* __restrict__ out,
                                           int e0, int E) {
    if (e0 >= E) return;   // E even, e0 even -> both edges valid

    int2 s2 = __ldg((const int2*)(src + e0));
    int2 d2 = __ldg((const int2*)(dst + e0));

    const float4* ep = (const float4*)(ea + (size_t)e0 * EF);
    float4 a0 = __ldg(ep + 0);
    float4 a1 = __ldg(ep + 1);
    float4 a2 = __ldg(ep + 2);
    float4 a3 = __ldg(ep + 3);

    // packed gathers: 16B halves + 4B s, both in the same 32B sector
    const float4* zp0 = z + (size_t)s2.x * 2;
    const float4* zp1 = z + (size_t)s2.y * 2;
    float4 yh0 = __ldg(zp0);
    float4 yh1 = __ldg(zp1);
    float  sc0 = __ldg((const float*)(zp0 + 1));
    float  sc1 = __ldg((const float*)(zp1 + 1));

    const __half2* h0 = (const __half2*)&yh0;
    const __half2* h1 = (const __half2*)&yh1;
    float2 p00 = __half22float2(h0[0]);
    float2 p01 = __half22float2(h0[1]);
    float2 p02 = __half22float2(h0[2]);
    float2 p03 = __half22float2(h0[3]);
    float2 p10 = __half22float2(h1[0]);
    float2 p11 = __half22float2(h1[1]);
    float2 p12 = __half22float2(h1[2]);
    float2 p13 = __half22float2(h1[3]);

    float m0 = sc0;
    m0 = fmaf(a0.x, p00.x, m0); m0 = fmaf(a0.y, p00.y, m0);
    m0 = fmaf(a0.z, p01.x, m0); m0 = fmaf(a0.w, p01.y, m0);
    m0 = fmaf(a1.x, p02.x, m0); m0 = fmaf(a1.y, p02.y, m0);
    m0 = fmaf(a1.z, p03.x, m0); m0 = fmaf(a1.w, p03.y, m0);

    float m1 = sc1;
    m1 = fmaf(a2.x, p10.x, m1); m1 = fmaf(a2.y, p10.y, m1);
    m1 = fmaf(a2.z, p11.x, m1); m1 = fmaf(a2.w, p11.y, m1);
    m1 = fmaf(a3.x, p12.x, m1); m1 = fmaf(a3.y, p12.y, m1);
    m1 = fmaf(a3.z, p13.x, m1); m1 = fmaf(a3.w, p13.y, m1);

    atomicAdd(out + d2.x, m0);
    atomicAdd(out + d2.y, m1);
}

// ---------------------------------------------------------------------------
// Fused edge kernel: blocks [0, NBE_1) -> h2i, rest -> i2i.
// ---------------------------------------------------------------------------
__global__ void edge_fused_kernel(const float* __restrict__ ea1,
                                  const int* __restrict__ src1,
                                  const int* __restrict__ dst1,
                                  const float* __restrict__ ea2,
                                  const int* __restrict__ src2,
                                  const int* __restrict__ dst2,
                                  float* __restrict__ out) {
    if (blockIdx.x < NBE_1) {
        int e0 = (blockIdx.x * TPB + threadIdx.x) * EPT;
        edge_work2(ea1, src1, dst1, g_z_house, out, e0, E1);
    } else {
        int e0 = ((blockIdx.x - NBE_1) * TPB + threadIdx.x) * EPT;
        edge_work2(ea2, src2, dst2, g_z_indivi, out, e0, E2);
    }
}

// ---------------------------------------------------------------------------
// launch — kernel launches ONLY (graph-capture clean)
// ---------------------------------------------------------------------------
extern "C" void kernel_launch(void* const* d_in, const int* in_sizes, int n_in,
                              void* d_out, int out_size) {
    const float* x_indivi      = (const float*)d_in[0];
    const float* x_house       = (const float*)d_in[1];
    const float* edge_attr_h2i = (const float*)d_in[2];
    const float* edge_attr_i2i = (const float*)d_in[3];
    const float* W_edge_h2i    = (const float*)d_in[4];
    const float* b_edge_h2i    = (const float*)d_in[5];
    const float* W_edge_i2i    = (const float*)d_in[6];
    const float* b_edge_i2i    = (const float*)d_in[7];
    const float* W_root_h2i    = (const float*)d_in[8];
    const float* bias_h2i      = (const float*)d_in[9];
    const float* W_root_i2i    = (const float*)d_in[10];
    const float* bias_i2i      = (const float*)d_in[11];
    const int*   src_h2i       = (const int*)d_in[12];
    const int*   dst_h2i       = (const int*)d_in[13];
    const int*   src_i2i       = (const int*)d_in[14];
    const int*   dst_i2i       = (const int*)d_in[15];
    float* out = (float*)d_out;

    prep_fused_kernel<<<NB_I + NB_H, TPB>>>(x_indivi, W_edge_i2i, b_edge_i2i,
                                            W_root_h2i, W_root_i2i,
                                            bias_h2i, bias_i2i,
                                            x_house, W_edge_h2i, b_edge_h2i,
                                            out);

    edge_fused_kernel<<<NBE_1 + NBE_2, TPB>>>(edge_attr_h2i, src_h2i, dst_h2i,
                                              edge_attr_i2i, src_i2i, dst_i2i,
                                              out);
}